// round 8
// baseline (speedup 1.0000x reference)
#include <cuda_runtime.h>
#include <math.h>

#define HID 64
#define NMAX 8192
#define EMAX 131072
#define NBLK 128
#define NTHR 512
#define NSTEP 10
#define RADIUS 7   // max circulant offset 193, npb=32 -> neighbor blocks in [b-7,b+7]

// ---------------- device scratch (no allocation allowed) ----------------
__device__ float  g_Cij[EMAX];
__device__ float  g_jc[EMAX];
__device__ float2 g_em2[EMAX];       // final messages (dumped post-loop)
__device__ float  g_f1[NMAX];
__device__ float  g_f2[NMAX];
__device__ float  g_Ci[NMAX];
__device__ float2 g_x2[2][NMAX];     // double-buffered x (per step parity)
__device__ float  g_npart[NBLK];
__device__ float  g_epart[NBLK];
__device__ unsigned g_step[NBLK];    // per-block published-x counter (reset per launch)
__device__ unsigned g_count;         // full-barrier arrivals (returns to 0)
__device__ unsigned g_sense;         // lsense derived at entry -> parity-safe
__device__ unsigned g_done;          // last-block finalize counter

// Fence-light full-grid barrier (release atomic arrival + acquire spin).
// All cross-block data after it is read via __ldcg (L2 = coherence point).
__device__ __forceinline__ void grid_barrier(unsigned& lsense) {
    __syncthreads();
    if (threadIdx.x == 0) {
        unsigned s = lsense ^ 1u;
        lsense = s;
        unsigned prev;
        asm volatile("atom.release.gpu.add.u32 %0, [%1], %2;"
                     : "=r"(prev) : "l"(&g_count), "r"(1u) : "memory");
        if (prev == gridDim.x - 1u) {
            g_count = 0u;
            asm volatile("st.release.gpu.u32 [%0], %1;"
                         :: "l"(&g_sense), "r"(s) : "memory");
        } else {
            unsigned v;
            do {
                asm volatile("ld.acquire.gpu.u32 %0, [%1];"
                             : "=r"(v) : "l"(&g_sense) : "memory");
                if (v == s) break;
                __nanosleep(32);
            } while (true);
        }
    }
    __syncthreads();
}

__global__ __launch_bounds__(NTHR, 1)
void k_fused(const float* __restrict__ J, const float* __restrict__ bias,
             const float* __restrict__ gat_W, const float* __restrict__ gat_a,
             const float* __restrict__ W1, const float* __restrict__ b1,
             const float* __restrict__ W2, const float* __restrict__ b2,
             const float* __restrict__ W3, const float* __restrict__ b3,
             const int* __restrict__ row, const int* __restrict__ col,
             const int* __restrict__ rev, const int* __restrict__ ru,
             const int* __restrict__ cu, const int* __restrict__ u2e,
             int N, int E, int Eu,
             float* __restrict__ out_readout, float* __restrict__ out_pw,
             float* __restrict__ out_scal, float* __restrict__ out_Ci,
             float* __restrict__ out_cij, float* __restrict__ out_dom)
{
    __shared__ float sW2[HID * HID];
    __shared__ float sh1[8][HID];
    __shared__ float sr[8][2][3];
    __shared__ float sred[NTHR];
    __shared__ float sJv[NTHR];          // block-local edge J values

    const int tid = threadIdx.x;
    const int b = blockIdx.x;
    const int gsize = NBLK * NTHR;
    const int DEG = E / N;               // uniform degree (16)
    unsigned lsense;
    asm volatile("ld.acquire.gpu.u32 %0, [%1];" : "=r"(lsense) : "l"(&g_sense));
    if (tid == 0) g_step[b] = 0u;        // reset before B-B (replay-safe)

    const int npb = (N + NBLK - 1) / NBLK;   // 32
    const int n0 = b * npb;
    const int n1 = min(N, n0 + npb);
    const int es = n0 * DEG;

    // ===== P1: own-chunk Jv gather into SMEM (block-local edges) =============
    for (int e = es + tid; e < n1 * DEG; e += NTHR) {
        int r = e / DEG;
        sJv[e - es] = J[(long long)r * N + col[e]];
    }
    __syncthreads();

    // ===== P2: node features + GAT f1/f2 + Ci MLP ============================
    for (int i = tid; i < HID * HID; i += NTHR) sW2[i] = W2[i];
    {
        int u = tid & 63;
        int nl8 = tid >> 6;
        const int npass = (npb + 7) / 8;
        for (int p = 0; p < npass; p++) {
            int node = n0 + p * 8 + nl8;
            int nc = node < n1 ? node : (n1 > 0 ? n1 - 1 : 0);
            float bb = bias[nc];
            int s0 = (nc - n0) * DEG;
            float Jsum = 0.0f;
            for (int k2 = 0; k2 < DEG; k2++) Jsum += sJv[s0 + k2];
            float ft0 = -bb, ft1 = bb, ft2 = (float)DEG, ft3 = Jsum;
            float wh = ft0 * gat_W[u] + ft1 * gat_W[HID + u]
                     + ft2 * gat_W[2 * HID + u] + ft3 * gat_W[3 * HID + u];
            float c1 = wh * gat_a[u];
            float c2 = wh * gat_a[HID + u];
            float h1 = b1[u] + ft0 * W1[u] + ft1 * W1[HID + u]
                     + ft2 * W1[2 * HID + u] + ft3 * W1[3 * HID + u];
            h1 = fmaxf(h1, 0.0f);
            sh1[nl8][u] = h1;
            #pragma unroll
            for (int off = 16; off > 0; off >>= 1) {
                c1 += __shfl_down_sync(0xffffffffu, c1, off);
                c2 += __shfl_down_sync(0xffffffffu, c2, off);
            }
            int half = u >> 5;
            if ((u & 31) == 0) { sr[nl8][half][0] = c1; sr[nl8][half][1] = c2; }
            __syncthreads();
            float h2 = b2[u];
            #pragma unroll 8
            for (int k2 = 0; k2 < HID; k2++) h2 += sh1[nl8][k2] * sW2[k2 * HID + u];
            h2 = fmaxf(h2, 0.0f);
            float cp = h2 * W3[u];
            #pragma unroll
            for (int off = 16; off > 0; off >>= 1)
                cp += __shfl_down_sync(0xffffffffu, cp, off);
            if ((u & 31) == 0) sr[nl8][half][2] = cp;
            __syncthreads();
            if (node < n1 && u == 0) {
                g_f1[node] = sr[nl8][0][0] + sr[nl8][1][0];
                g_f2[node] = sr[nl8][0][1] + sr[nl8][1][1];
                float Ci = sr[nl8][0][2] + sr[nl8][1][2] + b3[0];
                g_Ci[node] = Ci;
                out_Ci[node] = Ci;
            }
            __syncthreads();
        }
    }
    grid_barrier(lsense);                                   // B-A (f1/f2 global)

    // ===== P3: per-thread edge/node constants + x0 ==========================
    const int jl = tid >> 4;
    const int k = tid & 15;
    const int jn = n0 + jl;
    const bool nv = (jl < npb) && (jn < n1);
    const bool ev = nv && (k < DEG);
    int e_out = 0, i_nb = 0;
    float jc = 0.0f, C = 0.0f;
    if (ev) {
        e_out = jn * DEG + k;                 // directed edge (jn -> i_nb)
        i_nb = col[e_out];
        float f1j = __ldcg(&g_f1[jn]);
        float f2j = __ldcg(&g_f2[jn]);
        float f1i = __ldcg(&g_f1[i_nb]);
        float f2i = __ldcg(&g_f2[i_nb]);
        float a = f1j + f2i;
        float bb = f1i + f2j;
        a = (a >= 0.0f) ? a : 0.2f * a;       // leaky_relu 0.2
        bb = (bb >= 0.0f) ? bb : 0.2f * bb;
        C = 0.5f * (__expf(a) + __expf(bb));  // symmetric both directions
        jc = sJv[e_out - es] / C;
        g_Cij[e_out] = C;
        g_jc[e_out] = jc;
    }
    float csum = ev ? C : 0.0f;
    #pragma unroll
    for (int off = 8; off > 0; off >>= 1)
        csum += __shfl_xor_sync(0xffffffffu, csum, off);
    float dom = 1.0f, rdom = 1.0f, bx0 = 0.0f, bx1 = 0.0f, x0 = 0.0f, x1 = 0.0f;
    if (nv) {
        float d = g_Ci[jn] + csum;
        float sgn = (d > 0.0f) ? 1.0f : ((d < 0.0f) ? -1.0f : 0.0f);
        dom = sgn * fmaxf(fabsf(d), 0.1f);
        rdom = 1.0f / dom;
        float bs = bias[jn] * rdom;
        bx0 = -bs; bx1 = bs;
        x0 = bx0; x1 = bx1;                   // em0 = 0 -> nm = 0
        if (k == 0) {
            g_x2[0][jn] = make_float2(x0, x1);
            out_dom[jn] = dom;
        }
    }
    const float ejc  = __expf(jc);            // loop-invariant
    const float ejcm = __expf(-jc);
    float ei0 = 0.0f, ei1 = 0.0f;             // em on in-edge  (i_nb -> jn)
    float eo0 = 0.0f, eo1 = 0.0f;             // em on out-edge (jn -> i_nb)
    grid_barrier(lsense);                     // B-B (x0 + g_step resets global)

    // ===== P4: BP loop — neighborhood dataflow sync, no global barriers =====
    // Block b's nodes only read x of blocks [b-RADIUS, b+RADIUS] (circulant).
    // Double-buffered x kills WAR: reaching step t's store implies neighbors
    // published step t, hence consumed x_{t-1} (the buffer being overwritten).
    for (int t = 0; t < NSTEP; t++) {
        if (t > 0 && tid < 2 * RADIUS + 1) {
            int nb = (b + tid - RADIUS + NBLK) & (NBLK - 1);
            unsigned v;
            do {
                asm volatile("ld.acquire.gpu.u32 %0, [%1];"
                             : "=r"(v) : "l"(&g_step[nb]) : "memory");
                if (v >= (unsigned)t) break;
                __nanosleep(16);
            } while (true);
        }
        __syncthreads();                      // neighborhood x_t visible

        float ni0 = 0.0f, ni1 = 0.0f;
        if (ev) {
            float2 xi = __ldcg(&g_x2[t & 1][i_nb]);
            // out-message (jn->i): x_j and old in-message
            float eb0 = __expf(x0 - ei0);
            float eb1 = __expf(x1 - ei1);
            float t0 = fmaxf(ejc * eb0, ejcm * eb1);
            float t1 = fmaxf(ejcm * eb0, ejc * eb1);
            float inv = __frcp_rn(t0 + t1);
            float no0 = C * __logf(t0 * inv);
            float no1 = C * __logf(t1 * inv);
            // in-message (i->jn): x_i and old out-message
            float ec0 = __expf(xi.x - eo0);
            float ec1 = __expf(xi.y - eo1);
            float s0m = fmaxf(ejc * ec0, ejcm * ec1);
            float s1m = fmaxf(ejcm * ec0, ejc * ec1);
            float inv2 = __frcp_rn(s0m + s1m);
            ni0 = C * __logf(s0m * inv2);
            ni1 = C * __logf(s1m * inv2);
            eo0 = no0; eo1 = no1;
            ei0 = ni0; ei1 = ni1;
        }
        float m0 = ni0, m1 = ni1;
        #pragma unroll
        for (int off = 8; off > 0; off >>= 1) {
            m0 += __shfl_xor_sync(0xffffffffu, m0, off);
            m1 += __shfl_xor_sync(0xffffffffu, m1, off);
        }
        if (nv) {
            x0 = bx0 + m0 * rdom;
            x1 = bx1 + m1 * rdom;
            if (k == 0 && t != NSTEP - 1)
                g_x2[(t + 1) & 1][jn] = make_float2(x0, x1);
        }
        if (t != NSTEP - 1) {
            __syncthreads();                  // block's x_{t+1} stores done
            if (tid == 0)
                asm volatile("st.release.gpu.u32 [%0], %1;"
                             :: "l"(&g_step[b]), "r"((unsigned)(t + 1)) : "memory");
        }
    }

    // ===== P5: dump messages + readout + node entropy partials ==============
    if (ev) g_em2[e_out] = make_float2(eo0, eo1);
    float pnode = 0.0f;
    if (nv && k == 0) {
        float e0 = __expf(x0), e1 = __expf(x1);
        float inv = __frcp_rn(e0 + e1);
        float r0 = e0 * inv, r1 = e1 * inv;
        out_readout[2 * jn] = r0;
        out_readout[2 * jn + 1] = r1;
        float nH = -(r0 * __logf(r0 + 1e-16f) + r1 * __logf(r1 + 1e-16f));
        pnode = g_Ci[jn] * nH;
    }
    if (tid < 32) sred[tid] = 0.0f;
    __syncthreads();
    if (nv && k == 0 && jl < 32) sred[jl] = pnode;
    __syncthreads();
    if (tid == 0) {
        float s = 0.0f;
        for (int i2 = 0; i2 < npb && i2 < 32; i2++) s += sred[i2];
        g_npart[b] = s;
    }
    grid_barrier(lsense);                                   // B-L (em/readout global)

    // ===== P6: pairwise readout + edge entropy ==============================
    float pedge = 0.0f;
    for (int uu = b * NTHR + tid; uu < Eu; uu += gsize) {
        int e = u2e[uu];
        int er = rev[e];
        int ci = cu[uu], rj = ru[uu];
        float Js = __ldcg(&g_jc[e]);
        float Cu = __ldcg(&g_Cij[e]);
        float2 eme = __ldcg(&g_em2[e]);
        float2 emr = __ldcg(&g_em2[er]);
        float2 rci = __ldcg((const float2*)(out_readout + 2 * ci));
        float2 rrj = __ldcg((const float2*)(out_readout + 2 * rj));
        float ti0 = rci.x * __expf(-eme.x);
        float ti1 = rci.y * __expf(-eme.y);
        float tj0 = rrj.x * __expf(-emr.x);
        float tj1 = rrj.y * __expf(-emr.y);
        float eJ = __expf(Js), eJm = __expf(-Js);
        float p00 = eJ  * ti0 * tj0;
        float p01 = eJm * ti1 * tj0;
        float p10 = eJm * ti0 * tj1;
        float p11 = eJ  * ti1 * tj1;
        float invS = __frcp_rn(p00 + p01 + p10 + p11);
        float q00 = p00 * invS, q01 = p01 * invS;
        float q10 = p10 * invS, q11 = p11 * invS;
        out_pw[4 * uu]     = q00;
        out_pw[4 * uu + 1] = q01;
        out_pw[4 * uu + 2] = q10;
        out_pw[4 * uu + 3] = q11;
        out_cij[uu] = Cu;
        float eH = -(q00 * __logf(q00 + 1e-16f) + q01 * __logf(q01 + 1e-16f)
                   + q10 * __logf(q10 + 1e-16f) + q11 * __logf(q11 + 1e-16f));
        pedge += Cu * eH;
    }
    sred[tid] = pedge;
    __syncthreads();
    #pragma unroll
    for (int off = NTHR / 2; off > 0; off >>= 1) {
        if (tid < off) sred[tid] += sred[tid + off];
        __syncthreads();
    }

    // ===== P7: last-arriving block finalizes scalars ========================
    if (tid == 0) {
        g_epart[b] = sred[0];
        unsigned prev;
        asm volatile("atom.acq_rel.gpu.add.u32 %0, [%1], %2;"
                     : "=r"(prev) : "l"(&g_done), "r"(1u) : "memory");
        if (prev == (unsigned)(NBLK - 1)) {
            float ne = 0.0f, ed = 0.0f;
            for (int i2 = 0; i2 < NBLK; i2++) ne += __ldcg(&g_npart[i2]);
            for (int i2 = 0; i2 < NBLK; i2++) ed += __ldcg(&g_epart[i2]);
            out_scal[0] = ne + ed;
            out_scal[1] = ne;
            out_scal[2] = ed;
            g_done = 0u;     // reset for next graph replay
        }
    }
}

// ---------------- launcher ---------------------------------------------------
extern "C" void kernel_launch(void* const* d_in, const int* in_sizes, int n_in,
                              void* d_out, int out_size) {
    const float* J     = (const float*)d_in[0];
    const float* bias  = (const float*)d_in[1];
    const float* gat_W = (const float*)d_in[2];
    const float* gat_a = (const float*)d_in[3];
    const float* W1    = (const float*)d_in[4];
    const float* b1    = (const float*)d_in[5];
    const float* W2    = (const float*)d_in[6];
    const float* b2    = (const float*)d_in[7];
    const float* W3    = (const float*)d_in[8];
    const float* b3    = (const float*)d_in[9];
    const int*   row   = (const int*)d_in[10];
    const int*   col   = (const int*)d_in[11];
    const int*   rev   = (const int*)d_in[12];
    const int*   ru    = (const int*)d_in[13];
    const int*   cu    = (const int*)d_in[14];
    const int*   u2e   = (const int*)d_in[15];

    int N  = in_sizes[1];
    int E  = in_sizes[10];
    int Eu = in_sizes[13];

    float* out = (float*)d_out;
    float* out_readout = out;                    // [N,2]
    float* out_pw      = out + 2 * N;            // [Eu,4]
    float* out_scal    = out + 2 * N + 4 * Eu;   // 3 scalars
    float* out_Ci      = out_scal + 3;           // [N]
    float* out_cij     = out_Ci + N;             // [Eu]
    float* out_dom     = out_cij + Eu;           // [N]

    k_fused<<<NBLK, NTHR>>>(J, bias, gat_W, gat_a, W1, b1, W2, b2, W3, b3,
                            row, col, rev, ru, cu, u2e, N, E, Eu,
                            out_readout, out_pw, out_scal, out_Ci, out_cij,
                            out_dom);
}

// round 9
// speedup vs baseline: 1.2488x; 1.2488x over previous
#include <cuda_runtime.h>
#include <math.h>

#define HID 64
#define NMAX 8192
#define EMAX 131072
#define NBLK 144
#define NTHR 512
#define NSTEP 10

// ---------------- device scratch (no allocation allowed) ----------------
__device__ float  g_Cij[EMAX];
__device__ float  g_jc[EMAX];
__device__ float2 g_em2[EMAX];       // final messages (dumped post-loop)
__device__ float  g_f1[NMAX];
__device__ float  g_f2[NMAX];
__device__ float  g_Ci[NMAX];
__device__ float2 g_x2[NMAX];        // x = bx + nm/dom (the per-step global)
__device__ float2 g_lr2[NMAX];       // log-readout (for P6)
__device__ float  g_npart[NBLK];
__device__ float  g_epart[NBLK];
__device__ unsigned g_count;         // returns to 0 after every barrier
__device__ unsigned g_sense;         // lsense derived at entry -> parity-safe
__device__ unsigned g_done;          // last-block finalize counter (reset per launch)

// Fence-light sense-reversal barrier: release-atomic arrival, acquire-load
// spin. NO CCTL.IVALL — cross-block data after a barrier is read via __ldcg
// (L2 = coherence point; ldcg never hits a stale L1 line).
__device__ __forceinline__ void grid_barrier(unsigned& lsense) {
    __syncthreads();
    if (threadIdx.x == 0) {
        unsigned s = lsense ^ 1u;
        lsense = s;
        unsigned prev;
        asm volatile("atom.release.gpu.add.u32 %0, [%1], %2;"
                     : "=r"(prev) : "l"(&g_count), "r"(1u) : "memory");
        if (prev == gridDim.x - 1u) {
            g_count = 0u;   // ordered before the release store below
            asm volatile("st.release.gpu.u32 [%0], %1;"
                         :: "l"(&g_sense), "r"(s) : "memory");
        } else {
            unsigned v;
            do {
                asm volatile("ld.acquire.gpu.u32 %0, [%1];"
                             : "=r"(v) : "l"(&g_sense) : "memory");
                if (v == s) break;
                __nanosleep(32);
            } while (true);
        }
    }
    __syncthreads();
}

__global__ __launch_bounds__(NTHR, 1)
void k_fused(const float* __restrict__ J, const float* __restrict__ bias,
             const float* __restrict__ gat_W, const float* __restrict__ gat_a,
             const float* __restrict__ W1, const float* __restrict__ b1,
             const float* __restrict__ W2, const float* __restrict__ b2,
             const float* __restrict__ W3, const float* __restrict__ b3,
             const int* __restrict__ row, const int* __restrict__ col,
             const int* __restrict__ rev, const int* __restrict__ ru,
             const int* __restrict__ cu, const int* __restrict__ u2e,
             int N, int E, int Eu,
             float* __restrict__ out_readout, float* __restrict__ out_pw,
             float* __restrict__ out_scal, float* __restrict__ out_Ci,
             float* __restrict__ out_cij, float* __restrict__ out_dom)
{
    __shared__ float sW2[HID * HID];
    __shared__ float sh1[8][HID];
    __shared__ float sr[8][2][3];
    __shared__ float sred[NTHR];
    __shared__ float sJv[NTHR];          // block-local edge J values

    const int tid = threadIdx.x;
    const int b = blockIdx.x;
    const int gsize = NBLK * NTHR;
    const int DEG = E / N;               // uniform degree (16)
    unsigned lsense;
    asm volatile("ld.acquire.gpu.u32 %0, [%1];" : "=r"(lsense) : "l"(&g_sense));

    const int npb = (N + NBLK - 1) / NBLK;   // 29 for N=4096, NBLK=144
    const int n0 = b * npb;
    const int n1 = min(N, n0 + npb);
    const bool live = (n0 < n1);             // tail blocks may own no nodes
    const int es = n0 * DEG;

    if (live) {
        // ===== P1: own-chunk Jv gather into SMEM (block-local edges) =========
        for (int e = es + tid; e < n1 * DEG; e += NTHR) {
            int r = e / DEG;
            sJv[e - es] = J[(long long)r * N + col[e]];
        }
        __syncthreads();

        // ===== P2: node features + GAT f1/f2 + Ci MLP ========================
        for (int i = tid; i < HID * HID; i += NTHR) sW2[i] = W2[i];
        int u = tid & 63;
        int nl8 = tid >> 6;
        const int npass = (npb + 7) / 8;
        for (int p = 0; p < npass; p++) {
            int node = n0 + p * 8 + nl8;
            int nc = node < n1 ? node : n1 - 1;
            float bb = bias[nc];
            int s0 = (nc - n0) * DEG;
            float Jsum = 0.0f;
            for (int k2 = 0; k2 < DEG; k2++) Jsum += sJv[s0 + k2];
            float ft0 = -bb, ft1 = bb, ft2 = (float)DEG, ft3 = Jsum;
            float wh = ft0 * gat_W[u] + ft1 * gat_W[HID + u]
                     + ft2 * gat_W[2 * HID + u] + ft3 * gat_W[3 * HID + u];
            float c1 = wh * gat_a[u];
            float c2 = wh * gat_a[HID + u];
            float h1 = b1[u] + ft0 * W1[u] + ft1 * W1[HID + u]
                     + ft2 * W1[2 * HID + u] + ft3 * W1[3 * HID + u];
            h1 = fmaxf(h1, 0.0f);
            sh1[nl8][u] = h1;
            #pragma unroll
            for (int off = 16; off > 0; off >>= 1) {
                c1 += __shfl_down_sync(0xffffffffu, c1, off);
                c2 += __shfl_down_sync(0xffffffffu, c2, off);
            }
            int half = u >> 5;
            if ((u & 31) == 0) { sr[nl8][half][0] = c1; sr[nl8][half][1] = c2; }
            __syncthreads();
            float h2 = b2[u];
            #pragma unroll 8
            for (int k2 = 0; k2 < HID; k2++) h2 += sh1[nl8][k2] * sW2[k2 * HID + u];
            h2 = fmaxf(h2, 0.0f);
            float cp = h2 * W3[u];
            #pragma unroll
            for (int off = 16; off > 0; off >>= 1)
                cp += __shfl_down_sync(0xffffffffu, cp, off);
            if ((u & 31) == 0) sr[nl8][half][2] = cp;
            __syncthreads();
            if (node < n1 && u == 0) {
                g_f1[node] = sr[nl8][0][0] + sr[nl8][1][0];
                g_f2[node] = sr[nl8][0][1] + sr[nl8][1][1];
                float Ci = sr[nl8][0][2] + sr[nl8][1][2] + b3[0];
                g_Ci[node] = Ci;
                out_Ci[node] = Ci;
            }
            __syncthreads();
        }
    }
    grid_barrier(lsense);                                   // B-A (f1/f2 global)

    // ===== P3: per-thread edge/node constants + x0 ==========================
    const int jl = tid >> 4;
    const int k = tid & 15;
    const int jn = n0 + jl;
    const bool nv = live && (jl < npb) && (jn < n1);
    const bool ev = nv && (k < DEG);
    int e_out = 0, i_nb = 0;
    float jc = 0.0f, C = 0.0f;
    if (ev) {
        e_out = jn * DEG + k;                 // directed edge (jn -> i_nb)
        i_nb = col[e_out];
        float f1j = __ldcg(&g_f1[jn]);
        float f2j = __ldcg(&g_f2[jn]);
        float f1i = __ldcg(&g_f1[i_nb]);
        float f2i = __ldcg(&g_f2[i_nb]);
        float a = f1j + f2i;
        float bb = f1i + f2j;
        a = (a >= 0.0f) ? a : 0.2f * a;       // leaky_relu 0.2
        bb = (bb >= 0.0f) ? bb : 0.2f * bb;
        C = 0.5f * (__expf(a) + __expf(bb));  // symmetric both directions
        jc = sJv[e_out - es] / C;
        g_Cij[e_out] = C;
        g_jc[e_out] = jc;
    }
    float csum = ev ? C : 0.0f;
    #pragma unroll
    for (int off = 8; off > 0; off >>= 1)
        csum += __shfl_xor_sync(0xffffffffu, csum, off);
    float rdom = 1.0f, bx0 = 0.0f, bx1 = 0.0f, x0 = 0.0f, x1 = 0.0f;
    if (nv) {
        float d = g_Ci[jn] + csum;
        float sgn = (d > 0.0f) ? 1.0f : ((d < 0.0f) ? -1.0f : 0.0f);
        float dom = sgn * fmaxf(fabsf(d), 0.1f);
        rdom = 1.0f / dom;
        float bs = bias[jn] * rdom;
        bx0 = -bs; bx1 = bs;
        x0 = bx0; x1 = bx1;                   // em0 = 0 -> nm = 0
        if (k == 0) {
            g_x2[jn] = make_float2(x0, x1);
            out_dom[jn] = dom;
        }
    }
    float ei0 = 0.0f, ei1 = 0.0f;             // em on in-edge  (i_nb -> jn)
    float eo0 = 0.0f, eo1 = 0.0f;             // em on out-edge (jn -> i_nb)
    grid_barrier(lsense);                                   // B-B (x0 global)

    // ===== P4: BP loop — pure log-domain, 4 MUFU/thread/step ================
    for (int t = 0; t < NSTEP; t++) {
        float ni0 = 0.0f, ni1 = 0.0f;
        if (ev) {
            float2 xi = __ldcg(&g_x2[i_nb]); // only remote data per step
            // out-message (jn->i): log-max form, no exp needed for the max
            float d0 = x0 - ei0, d1 = x1 - ei1;
            float lt0 = fmaxf(jc + d0, d1 - jc);
            float lt1 = fmaxf(d0 - jc, jc + d1);
            float lse = fmaxf(lt0, lt1)
                      + __logf(1.0f + __expf(-fabsf(lt0 - lt1)));
            float no0 = C * (lt0 - lse);
            float no1 = C * (lt1 - lse);
            // in-message (i->jn)
            float c0 = xi.x - eo0, c1 = xi.y - eo1;
            float ls0 = fmaxf(jc + c0, c1 - jc);
            float ls1 = fmaxf(c0 - jc, jc + c1);
            float lsi = fmaxf(ls0, ls1)
                      + __logf(1.0f + __expf(-fabsf(ls0 - ls1)));
            ni0 = C * (ls0 - lsi);
            ni1 = C * (ls1 - lsi);
            eo0 = no0; eo1 = no1;
            ei0 = ni0; ei1 = ni1;
        }
        float m0 = ni0, m1 = ni1;
        #pragma unroll
        for (int off = 8; off > 0; off >>= 1) {
            m0 += __shfl_xor_sync(0xffffffffu, m0, off);
            m1 += __shfl_xor_sync(0xffffffffu, m1, off);
        }
        if (nv) {
            x0 = bx0 + m0 * rdom;
            x1 = bx1 + m1 * rdom;
            if (k == 0 && t != NSTEP - 1) g_x2[jn] = make_float2(x0, x1);
        }
        if (t != NSTEP - 1) grid_barrier(lsense);           // 9 in-loop barriers
    }

    // ===== P5: dump messages + readout (+log) + node entropy ================
    if (ev) g_em2[e_out] = make_float2(eo0, eo1);
    float pnode = 0.0f;
    if (nv && k == 0) {
        float lse = fmaxf(x0, x1) + __logf(1.0f + __expf(-fabsf(x0 - x1)));
        float lr0 = x0 - lse, lr1 = x1 - lse;
        float r0 = __expf(lr0), r1 = __expf(lr1);
        out_readout[2 * jn] = r0;
        out_readout[2 * jn + 1] = r1;
        g_lr2[jn] = make_float2(lr0, lr1);
        float nH = -(r0 * lr0 + r1 * lr1);
        pnode = g_Ci[jn] * nH;
    }
    if (tid < 32) sred[tid] = 0.0f;
    __syncthreads();
    if (nv && k == 0 && jl < 32) sred[jl] = pnode;
    __syncthreads();
    if (tid == 0) {
        float s = 0.0f;
        for (int i2 = 0; i2 < npb && i2 < 32; i2++) s += sred[i2];
        g_npart[b] = s;
    }
    grid_barrier(lsense);                                   // B-L (em/lr global)

    // ===== P6: pairwise readout + edge entropy (log-domain) =================
    float pedge = 0.0f;
    for (int uu = b * NTHR + tid; uu < Eu; uu += gsize) {
        int e = u2e[uu];
        int er = rev[e];
        int ci = cu[uu], rj = ru[uu];
        float Js = __ldcg(&g_jc[e]);
        float Cu = __ldcg(&g_Cij[e]);
        float2 eme = __ldcg(&g_em2[e]);
        float2 emr = __ldcg(&g_em2[er]);
        float2 li = __ldcg(&g_lr2[ci]);
        float2 lj = __ldcg(&g_lr2[rj]);
        float lti0 = li.x - eme.x, lti1 = li.y - eme.y;
        float ltj0 = lj.x - emr.x, ltj1 = lj.y - emr.y;
        float lp00 =  Js + lti0 + ltj0;
        float lp01 = -Js + lti1 + ltj0;
        float lp10 = -Js + lti0 + ltj1;
        float lp11 =  Js + lti1 + ltj1;
        float m = fmaxf(fmaxf(lp00, lp01), fmaxf(lp10, lp11));
        float e00 = __expf(lp00 - m), e01 = __expf(lp01 - m);
        float e10 = __expf(lp10 - m), e11 = __expf(lp11 - m);
        float S = e00 + e01 + e10 + e11;
        float invS = __frcp_rn(S);
        float lS = __logf(S);
        float q00 = e00 * invS, q01 = e01 * invS;
        float q10 = e10 * invS, q11 = e11 * invS;
        out_pw[4 * uu]     = q00;
        out_pw[4 * uu + 1] = q01;
        out_pw[4 * uu + 2] = q10;
        out_pw[4 * uu + 3] = q11;
        out_cij[uu] = Cu;
        float eH = -(q00 * (lp00 - m - lS) + q01 * (lp01 - m - lS)
                   + q10 * (lp10 - m - lS) + q11 * (lp11 - m - lS));
        pedge += Cu * eH;
    }
    sred[tid] = pedge;
    __syncthreads();
    #pragma unroll
    for (int off = NTHR / 2; off > 0; off >>= 1) {
        if (tid < off) sred[tid] += sred[tid + off];
        __syncthreads();
    }

    // ===== P7: last-arriving block finalizes scalars ========================
    if (tid == 0) {
        g_epart[b] = sred[0];
        unsigned prev;
        asm volatile("atom.acq_rel.gpu.add.u32 %0, [%1], %2;"
                     : "=r"(prev) : "l"(&g_done), "r"(1u) : "memory");
        if (prev == (unsigned)(NBLK - 1)) {
            float ne = 0.0f, ed = 0.0f;
            for (int i2 = 0; i2 < NBLK; i2++) ne += __ldcg(&g_npart[i2]);
            for (int i2 = 0; i2 < NBLK; i2++) ed += __ldcg(&g_epart[i2]);
            out_scal[0] = ne + ed;
            out_scal[1] = ne;
            out_scal[2] = ed;
            g_done = 0u;     // reset for next graph replay
        }
    }
}

// ---------------- launcher ---------------------------------------------------
extern "C" void kernel_launch(void* const* d_in, const int* in_sizes, int n_in,
                              void* d_out, int out_size) {
    const float* J     = (const float*)d_in[0];
    const float* bias  = (const float*)d_in[1];
    const float* gat_W = (const float*)d_in[2];
    const float* gat_a = (const float*)d_in[3];
    const float* W1    = (const float*)d_in[4];
    const float* b1    = (const float*)d_in[5];
    const float* W2    = (const float*)d_in[6];
    const float* b2    = (const float*)d_in[7];
    const float* W3    = (const float*)d_in[8];
    const float* b3    = (const float*)d_in[9];
    const int*   row   = (const int*)d_in[10];
    const int*   col   = (const int*)d_in[11];
    const int*   rev   = (const int*)d_in[12];
    const int*   ru    = (const int*)d_in[13];
    const int*   cu    = (const int*)d_in[14];
    const int*   u2e   = (const int*)d_in[15];

    int N  = in_sizes[1];
    int E  = in_sizes[10];
    int Eu = in_sizes[13];

    float* out = (float*)d_out;
    float* out_readout = out;                    // [N,2]
    float* out_pw      = out + 2 * N;            // [Eu,4]
    float* out_scal    = out + 2 * N + 4 * Eu;   // 3 scalars
    float* out_Ci      = out_scal + 3;           // [N]
    float* out_cij     = out_Ci + N;             // [Eu]
    float* out_dom     = out_cij + Eu;           // [N]

    k_fused<<<NBLK, NTHR>>>(J, bias, gat_W, gat_a, W1, b1, W2, b2, W3, b3,
                            row, col, rev, ru, cu, u2e, N, E, Eu,
                            out_readout, out_pw, out_scal, out_Ci, out_cij,
                            out_dom);
}